// round 14
// baseline (speedup 1.0000x reference)
#include <cuda_runtime.h>
#include <cstdint>
#include <cstddef>

#define BB 4
#define NN 512
#define DD 128
#define DH 64

// Scratch (no allocations allowed -> __device__ globals)
__device__ float g_Q [BB*NN*DH];
__device__ float g_K [BB*NN*DH];
__device__ float g_V [BB*NN*DH];
__device__ float g_Ni[BB*NN*DH];
__device__ float g_Nj[BB*NN*DH];
__device__ float g_A [BB*NN*NN];
__device__ float g_M [BB*NN];
__device__ float g_R [BB*NN];

// We^T packed fp16: g_WeH[k2*72 + n] = half2(We[2k2][n] lo, We[2k2+1][n] hi)
#define WH_STRIDE 72
__device__ uint32_t g_WeH[64 * WH_STRIDE];

// ============================ helpers ============================
__device__ __forceinline__ uint32_t smem_u32(const void* p) {
    uint32_t a;
    asm("{ .reg .u64 t; cvta.to.shared.u64 t, %1; cvt.u32.u64 %0, t; }" : "=r"(a) : "l"(p));
    return a;
}
__device__ __forceinline__ void cp16(uint32_t dst, const void* src) {
    asm volatile("cp.async.cg.shared.global [%0], [%1], 16;" :: "r"(dst), "l"(src));
}
// bulk TMA copy: contiguous global -> shared::cta, completion on mbarrier
__device__ __forceinline__ void cpbulk(uint32_t dst, const void* src, uint32_t bytes,
                                       uint32_t mbar) {
    asm volatile(
        "cp.async.bulk.shared::cta.global.mbarrier::complete_tx::bytes [%0], [%1], %2, [%3];"
        :: "r"(dst), "l"(src), "r"(bytes), "r"(mbar) : "memory");
}
#define MBARRIER_INIT(addr, cnt) \
    asm volatile("mbarrier.init.shared.b64 [%0], %1;" :: "r"(addr), "r"(cnt) : "memory")
#define MBARRIER_EXPECT_TX(addr, tx) \
    asm volatile("mbarrier.arrive.expect_tx.shared.b64 _, [%0], %1;" :: "r"(addr), "r"(tx) : "memory")
#define MBARRIER_WAIT_PARITY(addr, par) do {                                   \
    uint32_t _m = (addr); uint32_t _p = (par); uint32_t _done;                 \
    asm volatile("{ .reg .pred p; mbarrier.try_wait.parity.acquire.cta.shared::cta.b64 p, [%1], %2; selp.b32 %0, 1, 0, p; }" \
        : "=r"(_done) : "r"(_m), "r"(_p) : "memory");                          \
    if (!_done) {                                                              \
        asm volatile("{ .reg .pred P1; WL_%=: mbarrier.try_wait.parity.acquire.cta.shared::cta.b64 P1, [%0], %1, 0x989680; @P1 bra.uni WD_%=; bra.uni WL_%=; WD_%=: }" \
            :: "r"(_m), "r"(_p) : "memory");                                   \
    } } while(0)
// pack two f32 -> f16x2 (RN): h0 = lo, h1 = hi
__device__ __forceinline__ uint32_t ph2(float lo, float hi) {
    uint32_t u;
    asm("cvt.rn.f16x2.f32 %0, %1, %2;" : "=r"(u) : "f"(hi), "f"(lo));
    return u;
}
__device__ __forceinline__ void mma_f16(float& d0, float& d1, float& d2, float& d3,
                                        uint32_t a0, uint32_t a1, uint32_t a2, uint32_t a3,
                                        uint32_t b0, uint32_t b1) {
    asm volatile(
        "mma.sync.aligned.m16n8k16.row.col.f32.f16.f16.f32 "
        "{%0,%1,%2,%3}, {%4,%5,%6,%7}, {%8,%9}, {%0,%1,%2,%3};"
        : "+f"(d0), "+f"(d1), "+f"(d2), "+f"(d3)
        : "r"(a0), "r"(a1), "r"(a2), "r"(a3), "r"(b0), "r"(b1));
}

// ---------------------------------------------------------------------------
// Kernel 1: Q/K/V/Ni/Nj projections (Ni absorbs be).
// ---------------------------------------------------------------------------
__global__ __launch_bounds__(320) void proj_kernel(
    const float* __restrict__ x, const float* __restrict__ mask,
    const float* __restrict__ Wq, const float* __restrict__ bq,
    const float* __restrict__ Wk, const float* __restrict__ bk,
    const float* __restrict__ Wv, const float* __restrict__ bv,
    const float* __restrict__ Wni, const float* __restrict__ bni,
    const float* __restrict__ Wnj, const float* __restrict__ bnj,
    const float* __restrict__ be)
{
    __shared__ float xS[4][DD];
    int r0  = blockIdx.x * 4;
    int tid = threadIdx.x;
    for (int idx = tid; idx < 4 * DD; idx += 320)
        xS[idx >> 7][idx & 127] = x[r0 * DD + idx];
    __syncthreads();

    int mat = tid / 64;
    int d   = tid & 63;
    const float* W; float bias; float* dst; bool domask;
    switch (mat) {
        case 0:  W = Wq;  bias = bq[d];            dst = g_Q;  domask = true;  break;
        case 1:  W = Wk;  bias = bk[d];            dst = g_K;  domask = true;  break;
        case 2:  W = Wv;  bias = bv[d];            dst = g_V;  domask = true;  break;
        case 3:  W = Wni; bias = bni[d] + be[d];   dst = g_Ni; domask = false; break;
        default: W = Wnj; bias = bnj[d];           dst = g_Nj; domask = false; break;
    }
    float a0 = bias, a1 = bias, a2 = bias, a3 = bias;
    #pragma unroll 8
    for (int c = 0; c < DD; c++) {
        float wv = __ldg(&W[c * 64 + d]);
        a0 += xS[0][c] * wv;
        a1 += xS[1][c] * wv;
        a2 += xS[2][c] * wv;
        a3 += xS[3][c] * wv;
    }
    float acc[4] = {a0, a1, a2, a3};
    #pragma unroll
    for (int r = 0; r < 4; r++) {
        int row = r0 + r;
        float m = domask ? mask[row] : 1.0f;
        dst[row * 64 + d] = acc[r] * m;
    }
}

// ---------------------------------------------------------------------------
// Kernel 1b: We -> g_WeH: fp16-RN, k-adjacent half2 pairs, [64][72] padded.
// ---------------------------------------------------------------------------
__global__ void prep_weh_kernel(const float* __restrict__ We)
{
    int idx = blockIdx.x * 128 + threadIdx.x;     // 0 .. 4607
    int k2 = idx / WH_STRIDE;
    int n  = idx - k2 * WH_STRIDE;
    uint32_t val = 0;
    if (n < DH)
        val = ph2(We[(2 * k2) * DH + n], We[(2 * k2 + 1) * DH + n]);
    g_WeH[idx] = val;
}

// ---------------------------------------------------------------------------
// Kernel 2: fused  E = e@We (fp16 m16n8k16 mma.sync) -> e_out + logits.
// One CTA per (b,i). 256 thr = 8 warps, 2 CTAs/SM. TILE = 64 j-rows.
// A tiles loaded via bulk TMA (64 x 512B row copies into 544B slots -> keeps
// APAD=136 conflict-free fragment layout), double buffered with mbarriers.
// No per-thread LDGSTS in the steady state (that was the R11 binder).
// ---------------------------------------------------------------------------
#define APAD 136
#define TILE_R 64
#define OFF_WE   0                                  // 4608 u32
#define OFF_A0   4608
#define OFF_A1   (OFF_A0 + TILE_R * APAD)           // 13312
#define OFF_PS   (OFF_A1 + TILE_R * APAD)           // 22016 (2 x 64 x 2)
#define OFF_MBAR (OFF_PS + 256)                     // 22272: 2 barriers (u64)
#define SMEM_FLOATS (OFF_MBAR + 8)
#define SMEM_BYTES  (SMEM_FLOATS * 4)               // 89120

#define TILE_TX (TILE_R * 512)                      // 32768 bytes per tile

__global__ void __launch_bounds__(256, 2) fused_mma_kernel(
    const float* __restrict__ e, const float* __restrict__ mask,
    float* __restrict__ eout)
{
    extern __shared__ float smf[];
    uint32_t* WeHS = reinterpret_cast<uint32_t*>(smf + OFF_WE);
    float*    pSm  = smf + OFF_PS;                 // [2][64][2]
    uint32_t  sb   = smem_u32(smf);
    uint32_t  mbar0 = sb + OFF_MBAR * 4;
    uint32_t  mbar1 = mbar0 + 8;

    int tid  = threadIdx.x;
    int w    = tid >> 5, lane = tid & 31;
    int gid  = lane >> 2, tig = lane & 3;
    int wrow = (w >> 1) * 16;                      // 0,16,32,48
    int wcol = (w & 1) * 32;

    int b = blockIdx.y, i = blockIdx.x;
    int rowi = b * NN + i;
    float mi = mask[rowi];

    if (tid == 0) {
        MBARRIER_INIT(mbar0, 1);
        MBARRIER_INIT(mbar1, 1);
    }

    // per-thread Q / Ni for its 8 owned columns
    float2 q2[4], ni2[4];
    #pragma unroll
    for (int nt = 0; nt < 4; nt++) {
        int d0 = wcol + 8 * nt + 2 * tig;
        q2[nt]  = *(const float2*)&g_Q [rowi * 64 + d0];
        ni2[nt] = *(const float2*)&g_Ni[rowi * 64 + d0];
    }

    // stage WeH (4608 u32 = 1152 x 16B) via one-time cp.async
    {
        const char* wsrc = (const char*)g_WeH;
        #pragma unroll
        for (int k = 0; k < 5; k++) {
            int idx = tid + k * 256;
            if (idx < 1152)
                cp16(sb + OFF_WE * 4 + (uint32_t)idx * 16, wsrc + (size_t)idx * 16);
        }
        asm volatile("cp.async.commit_group;" ::: "memory");
    }

    const float* esrc = e + (size_t)rowi * NN * DD;

    __syncthreads();   // mbarrier init visible before any expect_tx/copies

    // kick tile 0 into buf0 via bulk TMA (64 x 512B row copies)
    if (tid == 0) {
        MBARRIER_EXPECT_TX(mbar0, TILE_TX);
        #pragma unroll 4
        for (int r = 0; r < TILE_R; r++)
            cpbulk(sb + (uint32_t)(OFF_A0 + r * APAD) * 4,
                   esrc + (size_t)r * DD, 512, mbar0);
    }

    asm volatile("cp.async.wait_group 0;" ::: "memory");   // WeH resident
    __syncthreads();

    #pragma unroll 1
    for (int t = 0; t < 8; t++) {
        int jt = t * TILE_R;

        // ---- prefetch epilogue operands for this tile (hidden behind MMA) ----
        float2 njR[2][4], kvR[2][4];
        float  mjR[2];
        #pragma unroll
        for (int rr = 0; rr < 2; rr++) {
            int rowj = b * NN + jt + wrow + 8 * rr + gid;
            mjR[rr] = __ldg(&mask[rowj]);
            #pragma unroll
            for (int nt = 0; nt < 4; nt++) {
                int d0 = wcol + 8 * nt + 2 * tig;
                njR[rr][nt] = *(const float2*)&g_Nj[rowj * 64 + d0];
                kvR[rr][nt] = *(const float2*)&g_K [rowj * 64 + d0];
            }
        }

        // refill the other buffer for tile t+1 (its last readers finished at
        // the epilogue __syncthreads of tile t-1)
        if (t < 7 && tid == 0) {
            uint32_t mb  = ((t + 1) & 1) ? mbar1 : mbar0;
            uint32_t ab  = ((t + 1) & 1) ? OFF_A1 : OFF_A0;
            const float* src = esrc + (size_t)(t + 1) * TILE_R * DD;
            MBARRIER_EXPECT_TX(mb, TILE_TX);
            #pragma unroll 4
            for (int r = 0; r < TILE_R; r++)
                cpbulk(sb + (uint32_t)(ab + r * APAD) * 4,
                       src + (size_t)r * DD, 512, mb);
        }

        // wait for this tile's data
        MBARRIER_WAIT_PARITY((t & 1) ? mbar1 : mbar0, (uint32_t)((t >> 1) & 1));

        const float*    A  = smf + ((t & 1) ? OFF_A1 : OFF_A0);
        const float*    Ab = A + (wrow + gid) * APAD + 2 * tig;
        const uint32_t* Bb = WeHS + tig * WH_STRIDE + wcol + gid;

        float acc[4][4];
        #pragma unroll
        for (int nt = 0; nt < 4; nt++)
            #pragma unroll
            for (int q = 0; q < 4; q++) acc[nt][q] = 0.f;

        #pragma unroll
        for (int ks = 0; ks < 8; ks++) {          // K16 chunks
            const float* pA = Ab + 16 * ks;
            float2 f0 = *(const float2*)(pA);
            float2 f1 = *(const float2*)(pA + 8 * APAD);
            float2 f2 = *(const float2*)(pA + 8);
            float2 f3 = *(const float2*)(pA + 8 * APAD + 8);
            uint32_t a0 = ph2(f0.x, f0.y);
            uint32_t a1 = ph2(f1.x, f1.y);
            uint32_t a2 = ph2(f2.x, f2.y);
            uint32_t a3 = ph2(f3.x, f3.y);
            const uint32_t* pB = Bb + 8 * ks * WH_STRIDE;
            #pragma unroll
            for (int nt = 0; nt < 4; nt++) {
                uint32_t b0 = pB[8 * nt];
                uint32_t b1 = pB[4 * WH_STRIDE + 8 * nt];
                mma_f16(acc[nt][0], acc[nt][1], acc[nt][2], acc[nt][3],
                        a0, a1, a2, a3, b0, b1);
            }
        }

        // ---- epilogue on fragments (all operands already in registers) ----
        float* pBuf = pSm + (t & 1) * 128;
        #pragma unroll
        for (int rr = 0; rr < 2; rr++) {
            int row  = wrow + 8 * rr + gid;
            int j    = jt + row;
            float me = mi * mjR[rr];
            float part = 0.f;
            float* outp = &eout[((size_t)rowi * NN + j) * 64];
            #pragma unroll
            for (int nt = 0; nt < 4; nt++) {
                int d0 = wcol + 8 * nt + 2 * tig;
                float e0 = (acc[nt][2 * rr    ] + ni2[nt].x + njR[rr][nt].x) * me;
                float e1 = (acc[nt][2 * rr + 1] + ni2[nt].y + njR[rr][nt].y) * me;
                __stcs((float2*)(outp + d0), make_float2(e0, e1));
                part += q2[nt].x * kvR[rr][nt].x * e0 + q2[nt].y * kvR[rr][nt].y * e1;
            }
            part += __shfl_xor_sync(0xffffffffu, part, 1);
            part += __shfl_xor_sync(0xffffffffu, part, 2);
            if (tig == 0) pBuf[row * 2 + (w & 1)] = part;
        }
        __syncthreads();
        if (tid < TILE_R) {
            int j = jt + tid, rowj = b * NN + j;
            float me = mi * mask[rowj];
            g_A[(size_t)rowi * NN + j] =
                (me > 0.f) ? (pBuf[tid * 2] + pBuf[tid * 2 + 1]) * 0.125f : -1.0e9f;
        }
        // no trailing sync: pSm double-buffered; A-buffer refill for t+2 is
        // gated by the epilogue __syncthreads above (all mainloop reads done).
    }
}

// ---------------------------------------------------------------------------
// Kernel 3: softmax over axis=1 (over i, per (b,j) column) -> max + 1/sumexp.
// ---------------------------------------------------------------------------
__global__ void colstats_kernel()
{
    int b  = blockIdx.y;
    int j  = blockIdx.x * 32 + threadIdx.x;
    int ty = threadIdx.y;
    const float* A = g_A + (size_t)b * NN * NN;

    float m = -1e30f;
    for (int i = ty; i < NN; i += 8) m = fmaxf(m, A[(size_t)i * NN + j]);
    float s = 0.f;
    for (int i = ty; i < NN; i += 8) s += __expf(A[(size_t)i * NN + j] - m);

    __shared__ float sm[8][32], ss[8][32];
    sm[ty][threadIdx.x] = m;
    ss[ty][threadIdx.x] = s;
    __syncthreads();
    if (ty == 0) {
        float M = sm[0][threadIdx.x];
        #pragma unroll
        for (int t = 1; t < 8; t++) M = fmaxf(M, sm[t][threadIdx.x]);
        float S = 0.f;
        #pragma unroll
        for (int t = 0; t < 8; t++) S += ss[t][threadIdx.x] * __expf(sm[t][threadIdx.x] - M);
        g_M[b * NN + j] = M;
        g_R[b * NN + j] = 1.0f / S;
    }
}

// ---------------------------------------------------------------------------
// Kernel 4: x_out[b,i,:] = sum_j (exp(A-M_j)*R_j) * V[b,j,:], masked.
// 512 threads / block, 8 i-rows per block.
// ---------------------------------------------------------------------------
__global__ __launch_bounds__(512) void xout_kernel(
    const float* __restrict__ mask, float* __restrict__ xout)
{
    int b  = blockIdx.y;
    int r  = threadIdx.x >> 6;     // 0..7
    int tx = threadIdx.x & 63;
    int i  = blockIdx.x * 8 + r;
    __shared__ float pS[8][NN];
    const float* Arow = g_A + ((size_t)(b * NN + i)) * NN;
    for (int jj = tx; jj < NN; jj += 64)
        pS[r][jj] = __expf(Arow[jj] - g_M[b * NN + jj]) * g_R[b * NN + jj];
    __syncthreads();

    float a0 = 0.f, a1 = 0.f, a2 = 0.f, a3 = 0.f;
    const float* Vb = g_V + (size_t)b * NN * 64;
    for (int j = 0; j < NN; j += 4) {
        a0 += pS[r][j    ] * __ldg(&Vb[(j    ) * 64 + tx]);
        a1 += pS[r][j + 1] * __ldg(&Vb[(j + 1) * 64 + tx]);
        a2 += pS[r][j + 2] * __ldg(&Vb[(j + 2) * 64 + tx]);
        a3 += pS[r][j + 3] * __ldg(&Vb[(j + 3) * 64 + tx]);
    }
    xout[(size_t)(b * NN + i) * 64 + tx] = (a0 + a1 + a2 + a3) * mask[b * NN + i];
}

// ---------------------------------------------------------------------------
extern "C" void kernel_launch(void* const* d_in, const int* in_sizes, int n_in,
                              void* d_out, int out_size)
{
    const float* x    = (const float*)d_in[0];
    const float* e    = (const float*)d_in[1];
    const float* mask = (const float*)d_in[2];
    const float* Wq   = (const float*)d_in[3];
    const float* bq   = (const float*)d_in[4];
    const float* Wk   = (const float*)d_in[5];
    const float* bk   = (const float*)d_in[6];
    const float* We   = (const float*)d_in[7];
    const float* be   = (const float*)d_in[8];
    const float* Wv   = (const float*)d_in[9];
    const float* bv   = (const float*)d_in[10];
    const float* Wni  = (const float*)d_in[11];
    const float* bni  = (const float*)d_in[12];
    const float* Wnj  = (const float*)d_in[13];
    const float* bnj  = (const float*)d_in[14];

    float* xout = (float*)d_out;
    float* eout = (float*)d_out + (size_t)BB * NN * DH;

    proj_kernel<<<(BB * NN) / 4, 320>>>(x, mask, Wq, bq, Wk, bk, Wv, bv,
                                        Wni, bni, Wnj, bnj, be);

    prep_weh_kernel<<<(64 * WH_STRIDE) / 128, 128>>>(We);

    cudaFuncSetAttribute(fused_mma_kernel,
                         cudaFuncAttributeMaxDynamicSharedMemorySize, SMEM_BYTES);
    fused_mma_kernel<<<dim3(NN, BB), 256, SMEM_BYTES>>>(e, mask, eout);

    colstats_kernel<<<dim3(NN / 32, BB), dim3(32, 8)>>>();

    xout_kernel<<<dim3(NN / 8, BB), 512>>>(mask, xout);
}